// round 14
// baseline (speedup 1.0000x reference)
#include <cuda_runtime.h>
#include <cuda_fp16.h>
#include <cstdint>

#define N_NODES 50000
#define N_EDGES 600000
#define D_IN 128
#define D_HID 256
#define D_OUT 128
#define SCAN_B 1024
#define NCHUNK ((N_NODES + SCAN_B - 1) / SCAN_B)   // 49

// ---------------- scratch (device globals; bound ONLY in device code) --------
__device__ float g_deg[N_NODES];
__device__ float g_dinv[N_NODES];
__device__ int   g_cnt[N_NODES];
__device__ int   g_rowptr[N_NODES + 1];
__device__ int   g_fill[N_NODES];
__device__ int   g_part[NCHUNK];
__device__ int   g_partscan[NCHUNK];
__device__ int   g_tick;
__device__ __align__(8) int2 g_csr[N_EDGES];   // {src, packed half2 {w,w}}
__device__ __align__(256) __half g_xh[N_NODES * D_IN];
__device__ __align__(256) __half g_agg[N_NODES * D_HID];
__device__ __align__(256) __half g_h[N_NODES * D_HID];
__device__ __align__(256) __half g_xw[N_NODES * D_OUT];
__device__ __align__(256) __half g_w1t[D_HID * D_IN];
__device__ __align__(256) __half g_w2t[D_HID * D_HID];
__device__ __align__(256) __half g_w3t[D_OUT * D_HID];

// ---------------- asm helpers ------------------------------------------------
__device__ __forceinline__ uint32_t smem_u32(const void* p) {
    uint32_t a;
    asm("{ .reg .u64 t; cvta.to.shared.u64 t, %1; cvt.u32.u64 %0, t; }"
        : "=r"(a) : "l"(p));
    return a;
}
__device__ __forceinline__ void ldsm4(uint32_t* r, uint32_t addr) {
    asm volatile("ldmatrix.sync.aligned.m8n8.x4.shared.b16 {%0,%1,%2,%3}, [%4];"
                 : "=r"(r[0]), "=r"(r[1]), "=r"(r[2]), "=r"(r[3]) : "r"(addr));
}
__device__ __forceinline__ void cpa16(uint32_t saddr, const void* g, bool pred) {
    int sz = pred ? 16 : 0;
    asm volatile("cp.async.ca.shared.global [%0], [%1], 16, %2;"
                 :: "r"(saddr), "l"(g), "r"(sz));
}
__device__ __forceinline__ void cpa_commit() {
    asm volatile("cp.async.commit_group;" ::: "memory");
}
template <int N>
__device__ __forceinline__ void cpa_wait() {
    asm volatile("cp.async.wait_group %0;" :: "n"(N) : "memory");
}
__device__ __forceinline__ void mma_f16(float* c, const uint32_t* a, const uint32_t* b) {
    asm volatile(
        "mma.sync.aligned.m16n8k16.row.col.f32.f16.f16.f32 "
        "{%0,%1,%2,%3}, {%4,%5,%6,%7}, {%8,%9}, {%0,%1,%2,%3};\n"
        : "+f"(c[0]), "+f"(c[1]), "+f"(c[2]), "+f"(c[3])
        : "r"(a[0]), "r"(a[1]), "r"(a[2]), "r"(a[3]), "r"(b[0]), "r"(b[1]));
}
__device__ __forceinline__ uint32_t sw(int r, int c) {
    return (uint32_t)r * 128u + (uint32_t)((c ^ (r & 7)) << 4);
}
__device__ __forceinline__ __half2 u2h2(unsigned int u) {
    __half2 h; *(unsigned int*)&h = u; return h;
}

// ---------------- GEMM body (unchanged; at legacy-HMMA ceiling) --------------
template <int K, int NTOT, bool RELU>
__device__ __forceinline__ void gemm_body(const __half* __restrict__ A,
                                          const __half* __restrict__ Bt,
                                          const float* __restrict__ bias,
                                          __half* __restrict__ C) {
    extern __shared__ __align__(16) char dsm[];
    uint32_t a_base = smem_u32(dsm);
    uint32_t b_base = a_base + 32768;

    int tid = threadIdx.x;
    int lane = tid & 31, warp = tid >> 5;
    int gid = lane >> 2, tig = lane & 3;
    int wm = warp >> 2, wn = warp & 3;
    int row0 = blockIdx.x * 128;
    int col0 = blockIdx.y * 128;

    float acc[4][4][4];
    #pragma unroll
    for (int mt = 0; mt < 4; mt++)
        #pragma unroll
        for (int nt = 0; nt < 4; nt++)
            #pragma unroll
            for (int q = 0; q < 4; q++) acc[mt][nt][q] = 0.f;

    constexpr int KT = K / 64;

    {
        #pragma unroll
        for (int i = 0; i < 4; i++) {
            int idx = tid + i * 256, r = idx >> 3, c = idx & 7;
            int gr = row0 + r;
            cpa16(a_base + sw(r, c), A + (size_t)gr * K + c * 8, gr < N_NODES);
        }
        #pragma unroll
        for (int i = 0; i < 4; i++) {
            int idx = tid + i * 256, r = idx >> 3, c = idx & 7;
            cpa16(b_base + sw(r, c), Bt + (size_t)(col0 + r) * K + c * 8, true);
        }
        cpa_commit();
    }

    #pragma unroll
    for (int t = 0; t < KT; t++) {
        int buf = t & 1;
        if (t + 1 < KT) {
            int nb_ = (t + 1) & 1, kb = (t + 1) * 64;
            #pragma unroll
            for (int i = 0; i < 4; i++) {
                int idx = tid + i * 256, r = idx >> 3, c = idx & 7;
                int gr = row0 + r;
                cpa16(a_base + nb_ * 16384 + sw(r, c),
                      A + (size_t)gr * K + kb + c * 8, gr < N_NODES);
            }
            #pragma unroll
            for (int i = 0; i < 4; i++) {
                int idx = tid + i * 256, r = idx >> 3, c = idx & 7;
                cpa16(b_base + nb_ * 16384 + sw(r, c),
                      Bt + (size_t)(col0 + r) * K + kb + c * 8, true);
            }
            cpa_commit();
            cpa_wait<1>();
        } else {
            cpa_wait<0>();
        }
        __syncthreads();

        uint32_t ab = a_base + buf * 16384;
        uint32_t bb = b_base + buf * 16384;
        #pragma unroll
        for (int ks = 0; ks < 4; ks++) {
            int c0 = ks * 2;
            uint32_t af[4][4], bf[4][2];
            #pragma unroll
            for (int mt = 0; mt < 4; mt++) {
                int r = wm * 64 + mt * 16 + (lane & 15);
                int c = c0 + (lane >> 4);
                ldsm4(af[mt], ab + sw(r, c));
            }
            #pragma unroll
            for (int bg = 0; bg < 2; bg++) {
                int r = wn * 32 + bg * 16 + ((lane >> 4) << 3) + (lane & 7);
                int c = c0 + ((lane >> 3) & 1);
                uint32_t q[4];
                ldsm4(q, bb + sw(r, c));
                bf[bg * 2][0] = q[0]; bf[bg * 2][1] = q[1];
                bf[bg * 2 + 1][0] = q[2]; bf[bg * 2 + 1][1] = q[3];
            }
            #pragma unroll
            for (int mt = 0; mt < 4; mt++)
                #pragma unroll
                for (int nt = 0; nt < 4; nt++)
                    mma_f16(acc[mt][nt], af[mt], bf[nt]);
        }
        __syncthreads();
    }

    #pragma unroll
    for (int mt = 0; mt < 4; mt++) {
        #pragma unroll
        for (int h = 0; h < 2; h++) {
            int r = row0 + wm * 64 + mt * 16 + gid + h * 8;
            if (r < N_NODES) {
                #pragma unroll
                for (int nt = 0; nt < 4; nt++) {
                    int c = col0 + wn * 32 + nt * 8 + 2 * tig;
                    float v0 = acc[mt][nt][h * 2 + 0];
                    float v1 = acc[mt][nt][h * 2 + 1];
                    if (RELU) {
                        v0 = fmaxf(v0 + __ldg(&bias[c]), 0.f);
                        v1 = fmaxf(v1 + __ldg(&bias[c + 1]), 0.f);
                    }
                    *(__half2*)(C + (size_t)r * NTOT + c) = __floats2half2_rn(v0, v1);
                }
            }
        }
    }
}

__global__ __launch_bounds__(256) void k_gemm1(const float* __restrict__ b1) {
    gemm_body<128, 256, true>(g_agg, g_w1t, b1, g_h);
}
__global__ __launch_bounds__(256) void k_gemm2(const float* __restrict__ b2) {
    gemm_body<256, 256, true>(g_agg, g_w2t, b2, g_h);
}
__global__ __launch_bounds__(256) void k_gemm3() {
    gemm_body<256, 128, false>(g_h, g_w3t, nullptr, g_xw);
}

// ---------------- prep split: CSR chain vs conversions (parallel streams) ----
__global__ void k_eprep(const float* __restrict__ ew_raw,
                        const int* __restrict__ dst) {
    int i = blockIdx.x * blockDim.x + threadIdx.x;
    if (i < N_EDGES) {
        float w = ew_raw[i];
        float sp = fmaxf(w, 0.0f) + log1pf(expf(-fabsf(w)));
        int d = dst[i];
        atomicAdd(&g_deg[d], sp);
        atomicAdd(&g_cnt[d], 1);
    }
}

#define XQ (N_NODES * D_IN / 4)
#define WT1 (D_HID * D_IN)
#define WT2 (D_HID * D_HID)
#define WT3 (D_OUT * D_HID)
#define CONV_TOTAL (XQ + WT1 + WT2 + WT3)

__global__ void k_conv(const float* __restrict__ x,
                       const float* __restrict__ W1,
                       const float* __restrict__ W2,
                       const float* __restrict__ W3) {
    int j = blockIdx.x * blockDim.x + threadIdx.x;
    if (j < XQ) {
        float4 v = __ldg(&((const float4*)x)[j]);
        uint2 u;
        *(__half2*)&u.x = __floats2half2_rn(v.x, v.y);
        *(__half2*)&u.y = __floats2half2_rn(v.z, v.w);
        ((uint2*)g_xh)[j] = u;
        return;
    }
    j -= XQ;
    if (j < WT1) {
        int n = j / D_IN, k = j % D_IN;
        g_w1t[j] = __float2half_rn(W1[k * D_HID + n]);
        return;
    }
    j -= WT1;
    if (j < WT2) {
        int n = j / D_HID, k = j % D_HID;
        g_w2t[j] = __float2half_rn(W2[k * D_HID + n]);
        return;
    }
    j -= WT2;
    if (j < WT3) {
        int n = j / D_HID, k = j % D_HID;
        g_w3t[j] = __float2half_rn(W3[k * D_OUT + n]);
    }
}

// ---------------- scan -------------------------------------------------------
__global__ void k_scan() {
    __shared__ int s[SCAN_B];
    __shared__ bool isLast;
    int b = blockIdx.x, tid = threadIdx.x;
    int i = b * SCAN_B + tid;
    if (i < N_NODES) g_dinv[i] = rsqrtf(g_deg[i] + 1.0f);
    int v = (i < N_NODES) ? g_cnt[i] : 0;
    s[tid] = v;
    __syncthreads();
    #pragma unroll
    for (int off = 1; off < SCAN_B; off <<= 1) {
        int t = (tid >= off) ? s[tid - off] : 0;
        __syncthreads();
        s[tid] += t;
        __syncthreads();
    }
    int excl = s[tid] - v;
    if (i < N_NODES) { g_rowptr[i] = excl; g_fill[i] = excl; }
    if (i == N_NODES - 1) g_rowptr[N_NODES] = s[tid];
    if (tid == SCAN_B - 1) g_part[b] = s[tid];

    __threadfence();
    __syncthreads();
    if (tid == 0) isLast = (atomicAdd(&g_tick, 1) == NCHUNK - 1);
    __syncthreads();
    if (!isLast) return;
    __threadfence();

    int v2 = (tid < NCHUNK) ? g_part[tid] : 0;
    s[tid] = (tid < 64) ? v2 : 0;
    __syncthreads();
    #pragma unroll
    for (int off = 1; off < 64; off <<= 1) {
        int t = (tid >= off && tid < 64) ? s[tid - off] : 0;
        __syncthreads();
        if (tid < 64) s[tid] += t;
        __syncthreads();
    }
    if (tid < NCHUNK) g_partscan[tid] = s[tid] - v2;
    if (tid == 0) g_tick = 0;
}

// ---------------- place: recompute softplus, pack int2, deferred reset -------
__global__ void k_place(const float* __restrict__ ew_raw,
                        const int* __restrict__ src,
                        const int* __restrict__ dst) {
    int i = blockIdx.x * blockDim.x + threadIdx.x;
    if (i < N_EDGES) {
        float rw = ew_raw[i];
        float sp = fmaxf(rw, 0.0f) + log1pf(expf(-fabsf(rw)));
        int s = src[i], d = dst[i];
        float w = g_dinv[s] * sp * g_dinv[d];
        unsigned int hw = (unsigned int)__half_as_ushort(__float2half_rn(w));
        int pos = atomicAdd(&g_fill[d], 1) + g_partscan[d >> 10];
        g_csr[pos] = make_int2(s, (int)(hw | (hw << 16)));
    }
    if (i < N_NODES) { g_deg[i] = 0.0f; g_cnt[i] = 0; }
}

// ---------------- aggregation: 8-edge MLP groups, int2 CSR -------------------
template <int DIM, bool OUT_FLOAT>
__device__ __forceinline__ void agg_half_body(const __half* __restrict__ src,
                                              __half* __restrict__ dsth,
                                              float* __restrict__ dstf,
                                              const float* __restrict__ bias) {
    int warp = (blockIdx.x * blockDim.x + threadIdx.x) >> 5;
    int lane = threadIdx.x & 31;
    if (warp >= N_NODES) return;
    constexpr int V = DIM / 128;

    int start = g_rowptr[warp] + g_partscan[warp >> 10];
    int end   = g_rowptr[warp + 1] + g_partscan[(warp + 1) >> 10];
    float di = g_dinv[warp];
    float w0 = di * di;

    float2 acc[2 * V];
    {
        if (V == 1) {
            uint2 u = __ldg(&((const uint2*)(src + (size_t)warp * DIM))[lane]);
            float2 f0 = __half22float2(u2h2(u.x)), f1 = __half22float2(u2h2(u.y));
            acc[0] = make_float2(w0 * f0.x, w0 * f0.y);
            acc[1] = make_float2(w0 * f1.x, w0 * f1.y);
        } else {
            uint4 u = __ldg(&((const uint4*)(src + (size_t)warp * DIM))[lane]);
            float2 f0 = __half22float2(u2h2(u.x)), f1 = __half22float2(u2h2(u.y));
            float2 f2 = __half22float2(u2h2(u.z)), f3 = __half22float2(u2h2(u.w));
            acc[0] = make_float2(w0 * f0.x, w0 * f0.y);
            acc[1] = make_float2(w0 * f1.x, w0 * f1.y);
            acc[2] = make_float2(w0 * f2.x, w0 * f2.y);
            acc[3] = make_float2(w0 * f3.x, w0 * f3.y);
        }
    }

    int e = start;
    for (; e + 7 < end; e += 8) {
        int2 ce[8];
        #pragma unroll
        for (int q = 0; q < 8; q++) ce[q] = g_csr[e + q];
        if (V == 1) {
            uint2 a[8];
            #pragma unroll
            for (int q = 0; q < 8; q++)
                a[q] = __ldg(&((const uint2*)(src + (size_t)ce[q].x * DIM))[lane]);
            #pragma unroll
            for (int g2 = 0; g2 < 2; g2++) {
                int o = g2 * 4;
                __half2 h0 = __hmul2(u2h2(a[o].x), u2h2((unsigned)ce[o].y));
                __half2 h1 = __hmul2(u2h2(a[o].y), u2h2((unsigned)ce[o].y));
                #pragma unroll
                for (int q = 1; q < 4; q++) {
                    __half2 wq = u2h2((unsigned)ce[o + q].y);
                    h0 = __hfma2(u2h2(a[o + q].x), wq, h0);
                    h1 = __hfma2(u2h2(a[o + q].y), wq, h1);
                }
                float2 f0 = __half22float2(h0), f1 = __half22float2(h1);
                acc[0].x += f0.x; acc[0].y += f0.y;
                acc[1].x += f1.x; acc[1].y += f1.y;
            }
        } else {
            uint4 a[8];
            #pragma unroll
            for (int q = 0; q < 8; q++)
                a[q] = __ldg(&((const uint4*)(src + (size_t)ce[q].x * DIM))[lane]);
            #pragma unroll
            for (int g2 = 0; g2 < 2; g2++) {
                int o = g2 * 4;
                __half2 w_ = u2h2((unsigned)ce[o].y);
                __half2 h0 = __hmul2(u2h2(a[o].x), w_);
                __half2 h1 = __hmul2(u2h2(a[o].y), w_);
                __half2 h2 = __hmul2(u2h2(a[o].z), w_);
                __half2 h3 = __hmul2(u2h2(a[o].w), w_);
                #pragma unroll
                for (int q = 1; q < 4; q++) {
                    __half2 wq = u2h2((unsigned)ce[o + q].y);
                    h0 = __hfma2(u2h2(a[o + q].x), wq, h0);
                    h1 = __hfma2(u2h2(a[o + q].y), wq, h1);
                    h2 = __hfma2(u2h2(a[o + q].z), wq, h2);
                    h3 = __hfma2(u2h2(a[o + q].w), wq, h3);
                }
                float2 f0 = __half22float2(h0), f1 = __half22float2(h1);
                float2 f2 = __half22float2(h2), f3 = __half22float2(h3);
                acc[0].x += f0.x; acc[0].y += f0.y;
                acc[1].x += f1.x; acc[1].y += f1.y;
                acc[2].x += f2.x; acc[2].y += f2.y;
                acc[3].x += f3.x; acc[3].y += f3.y;
            }
        }
    }
    for (; e + 3 < end; e += 4) {
        int2 ce[4];
        #pragma unroll
        for (int q = 0; q < 4; q++) ce[q] = g_csr[e + q];
        if (V == 1) {
            uint2 a[4];
            #pragma unroll
            for (int q = 0; q < 4; q++)
                a[q] = __ldg(&((const uint2*)(src + (size_t)ce[q].x * DIM))[lane]);
            __half2 h0 = __hmul2(u2h2(a[0].x), u2h2((unsigned)ce[0].y));
            __half2 h1 = __hmul2(u2h2(a[0].y), u2h2((unsigned)ce[0].y));
            #pragma unroll
            for (int q = 1; q < 4; q++) {
                __half2 wq = u2h2((unsigned)ce[q].y);
                h0 = __hfma2(u2h2(a[q].x), wq, h0);
                h1 = __hfma2(u2h2(a[q].y), wq, h1);
            }
            float2 f0 = __half22float2(h0), f1 = __half22float2(h1);
            acc[0].x += f0.x; acc[0].y += f0.y;
            acc[1].x += f1.x; acc[1].y += f1.y;
        } else {
            uint4 a[4];
            #pragma unroll
            for (int q = 0; q < 4; q++)
                a[q] = __ldg(&((const uint4*)(src + (size_t)ce[q].x * DIM))[lane]);
            __half2 w_ = u2h2((unsigned)ce[0].y);
            __half2 h0 = __hmul2(u2h2(a[0].x), w_);
            __half2 h1 = __hmul2(u2h2(a[0].y), w_);
            __half2 h2 = __hmul2(u2h2(a[0].z), w_);
            __half2 h3 = __hmul2(u2h2(a[0].w), w_);
            #pragma unroll
            for (int q = 1; q < 4; q++) {
                __half2 wq = u2h2((unsigned)ce[q].y);
                h0 = __hfma2(u2h2(a[q].x), wq, h0);
                h1 = __hfma2(u2h2(a[q].y), wq, h1);
                h2 = __hfma2(u2h2(a[q].z), wq, h2);
                h3 = __hfma2(u2h2(a[q].w), wq, h3);
            }
            float2 f0 = __half22float2(h0), f1 = __half22float2(h1);
            float2 f2 = __half22float2(h2), f3 = __half22float2(h3);
            acc[0].x += f0.x; acc[0].y += f0.y;
            acc[1].x += f1.x; acc[1].y += f1.y;
            acc[2].x += f2.x; acc[2].y += f2.y;
            acc[3].x += f3.x; acc[3].y += f3.y;
        }
    }
    for (; e < end; e++) {
        int2 ce = g_csr[e];
        float w1 = __half2float(__low2half(u2h2((unsigned)ce.y)));
        if (V == 1) {
            uint2 a = __ldg(&((const uint2*)(src + (size_t)ce.x * DIM))[lane]);
            float2 f0 = __half22float2(u2h2(a.x)), f1 = __half22float2(u2h2(a.y));
            acc[0].x += w1 * f0.x; acc[0].y += w1 * f0.y;
            acc[1].x += w1 * f1.x; acc[1].y += w1 * f1.y;
        } else {
            uint4 a = __ldg(&((const uint4*)(src + (size_t)ce.x * DIM))[lane]);
            float2 f0 = __half22float2(u2h2(a.x)), f1 = __half22float2(u2h2(a.y));
            float2 f2 = __half22float2(u2h2(a.z)), f3 = __half22float2(u2h2(a.w));
            acc[0].x += w1 * f0.x; acc[0].y += w1 * f0.y;
            acc[1].x += w1 * f1.x; acc[1].y += w1 * f1.y;
            acc[2].x += w1 * f2.x; acc[2].y += w1 * f2.y;
            acc[3].x += w1 * f3.x; acc[3].y += w1 * f3.y;
        }
    }

    if (OUT_FLOAT) {
        float4 b4 = __ldg(&((const float4*)bias)[lane]);
        ((float4*)(dstf + (size_t)warp * DIM))[lane] =
            make_float4(acc[0].x + b4.x, acc[0].y + b4.y,
                        acc[1].x + b4.z, acc[1].y + b4.w);
    } else {
        if (V == 1) {
            uint2 u;
            *(__half2*)&u.x = __floats2half2_rn(acc[0].x, acc[0].y);
            *(__half2*)&u.y = __floats2half2_rn(acc[1].x, acc[1].y);
            ((uint2*)(dsth + (size_t)warp * DIM))[lane] = u;
        } else {
            uint4 u;
            *(__half2*)&u.x = __floats2half2_rn(acc[0].x, acc[0].y);
            *(__half2*)&u.y = __floats2half2_rn(acc[1].x, acc[1].y);
            *(__half2*)&u.z = __floats2half2_rn(acc[2].x, acc[2].y);
            *(__half2*)&u.w = __floats2half2_rn(acc[3].x, acc[3].y);
            ((uint4*)(dsth + (size_t)warp * DIM))[lane] = u;
        }
    }
}

__global__ void k_agg_x() {
    agg_half_body<128, false>(g_xh, g_agg, nullptr, nullptr);
}
__global__ void k_agg_h() {
    agg_half_body<256, false>(g_h, g_agg, nullptr, nullptr);
}
__global__ void k_agg_out(float* __restrict__ out, const float* __restrict__ b3) {
    agg_half_body<128, true>(g_xw, nullptr, out, b3);
}

// ---------------- launch -----------------------------------------------------
extern "C" void kernel_launch(void* const* d_in, const int* in_sizes, int n_in,
                              void* d_out, int out_size) {
    const float* x      = (const float*)d_in[0];
    const int*   ei     = (const int*)d_in[1];   // int32 (harness downcasts int64)
    const float* ew_raw = (const float*)d_in[2];
    const float* W1     = (const float*)d_in[3];
    const float* b1     = (const float*)d_in[4];
    const float* W2     = (const float*)d_in[5];
    const float* b2     = (const float*)d_in[6];
    const float* W3     = (const float*)d_in[7];
    const float* b3     = (const float*)d_in[8];
    float* out          = (float*)d_out;

    const int* src = ei;
    const int* dst = ei + N_EDGES;

    const int T = 256;
    int nb_edges = (N_EDGES + T - 1) / T;
    int agg_blocks = (N_NODES * 32 + T - 1) / T;
    int gm = (N_NODES + 127) / 128;   // 391

    const int GEMM_SMEM = 65536;
    cudaFuncSetAttribute(k_gemm1, cudaFuncAttributeMaxDynamicSharedMemorySize, GEMM_SMEM);
    cudaFuncSetAttribute(k_gemm2, cudaFuncAttributeMaxDynamicSharedMemorySize, GEMM_SMEM);
    cudaFuncSetAttribute(k_gemm3, cudaFuncAttributeMaxDynamicSharedMemorySize, GEMM_SMEM);

    // side stream for conversions (created per call; host resources only)
    cudaStream_t s1;
    cudaStreamCreate(&s1);
    cudaEvent_t e0, e1;
    cudaEventCreate(&e0);
    cudaEventCreate(&e1);

    // fork: conversions on s1, CSR chain on main stream
    cudaEventRecord(e0, 0);
    cudaStreamWaitEvent(s1, e0, 0);
    k_conv<<<(CONV_TOTAL + T - 1) / T, T, 0, s1>>>(x, W1, W2, W3);
    cudaEventRecord(e1, s1);

    k_eprep<<<nb_edges, T>>>(ew_raw, dst);
    k_scan<<<NCHUNK, SCAN_B>>>();
    k_place<<<nb_edges, T>>>(ew_raw, src, dst);

    // join: agg_x needs g_xh (s1) + CSR (main)
    cudaStreamWaitEvent(0, e1, 0);

    k_agg_x<<<agg_blocks, T>>>();
    k_gemm1<<<dim3(gm, 2), 256, GEMM_SMEM>>>(b1);

    k_agg_h<<<agg_blocks, T>>>();
    k_gemm2<<<dim3(gm, 2), 256, GEMM_SMEM>>>(b2);

    k_gemm3<<<dim3(gm, 1), 256, GEMM_SMEM>>>();
    k_agg_out<<<agg_blocks, T>>>(out, b3);
    // streams/events intentionally not destroyed: kernel_launch is called only
    // a handful of times (correctness + capture); destroying mid-capture risks
    // invalidating the captured graph. No device memory is involved.
}

// round 15
// speedup vs baseline: 1.0229x; 1.0229x over previous
#include <cuda_runtime.h>
#include <cuda_fp16.h>
#include <cstdint>

#define N_NODES 50000
#define N_EDGES 600000
#define D_IN 128
#define D_HID 256
#define D_OUT 128
#define SCAN_B 1024
#define NCHUNK ((N_NODES + SCAN_B - 1) / SCAN_B)   // 49

// ---------------- scratch (device globals; bound ONLY in device code) --------
__device__ float g_deg[N_NODES];
__device__ float g_dinv[N_NODES];
__device__ int   g_cnt[N_NODES];
__device__ int   g_rowptr[N_NODES + 1];
__device__ int   g_fill[N_NODES];
__device__ int   g_part[NCHUNK];
__device__ int   g_partscan[NCHUNK];
__device__ int   g_tick;
__device__ __align__(8) int2 g_csr[N_EDGES];   // {src, packed half2 {w,w}}
__device__ __align__(256) __half g_xh[N_NODES * D_IN];
__device__ __align__(256) __half g_agg[N_NODES * D_HID];
__device__ __align__(256) __half g_h[N_NODES * D_HID];
__device__ __align__(256) __half g_xw[N_NODES * D_OUT];
__device__ __align__(256) __half g_w1t[D_HID * D_IN];
__device__ __align__(256) __half g_w2t[D_HID * D_HID];
__device__ __align__(256) __half g_w3t[D_OUT * D_HID];

// ---------------- asm helpers ------------------------------------------------
__device__ __forceinline__ uint32_t smem_u32(const void* p) {
    uint32_t a;
    asm("{ .reg .u64 t; cvta.to.shared.u64 t, %1; cvt.u32.u64 %0, t; }"
        : "=r"(a) : "l"(p));
    return a;
}
__device__ __forceinline__ void ldsm4(uint32_t* r, uint32_t addr) {
    asm volatile("ldmatrix.sync.aligned.m8n8.x4.shared.b16 {%0,%1,%2,%3}, [%4];"
                 : "=r"(r[0]), "=r"(r[1]), "=r"(r[2]), "=r"(r[3]) : "r"(addr));
}
__device__ __forceinline__ void cpa16(uint32_t saddr, const void* g, bool pred) {
    int sz = pred ? 16 : 0;
    asm volatile("cp.async.ca.shared.global [%0], [%1], 16, %2;"
                 :: "r"(saddr), "l"(g), "r"(sz));
}
__device__ __forceinline__ void cpa_commit() {
    asm volatile("cp.async.commit_group;" ::: "memory");
}
template <int N>
__device__ __forceinline__ void cpa_wait() {
    asm volatile("cp.async.wait_group %0;" :: "n"(N) : "memory");
}
__device__ __forceinline__ void mma_f16(float* c, const uint32_t* a, const uint32_t* b) {
    asm volatile(
        "mma.sync.aligned.m16n8k16.row.col.f32.f16.f16.f32 "
        "{%0,%1,%2,%3}, {%4,%5,%6,%7}, {%8,%9}, {%0,%1,%2,%3};\n"
        : "+f"(c[0]), "+f"(c[1]), "+f"(c[2]), "+f"(c[3])
        : "r"(a[0]), "r"(a[1]), "r"(a[2]), "r"(a[3]), "r"(b[0]), "r"(b[1]));
}
__device__ __forceinline__ uint32_t sw(int r, int c) {
    return (uint32_t)r * 128u + (uint32_t)((c ^ (r & 7)) << 4);
}
__device__ __forceinline__ __half2 u2h2(unsigned int u) {
    __half2 h; *(unsigned int*)&h = u; return h;
}

// ---------------- GEMM body (unchanged; at legacy-HMMA ceiling) --------------
template <int K, int NTOT, bool RELU>
__device__ __forceinline__ void gemm_body(const __half* __restrict__ A,
                                          const __half* __restrict__ Bt,
                                          const float* __restrict__ bias,
                                          __half* __restrict__ C) {
    extern __shared__ __align__(16) char dsm[];
    uint32_t a_base = smem_u32(dsm);
    uint32_t b_base = a_base + 32768;

    int tid = threadIdx.x;
    int lane = tid & 31, warp = tid >> 5;
    int gid = lane >> 2, tig = lane & 3;
    int wm = warp >> 2, wn = warp & 3;
    int row0 = blockIdx.x * 128;
    int col0 = blockIdx.y * 128;

    float acc[4][4][4];
    #pragma unroll
    for (int mt = 0; mt < 4; mt++)
        #pragma unroll
        for (int nt = 0; nt < 4; nt++)
            #pragma unroll
            for (int q = 0; q < 4; q++) acc[mt][nt][q] = 0.f;

    constexpr int KT = K / 64;

    {
        #pragma unroll
        for (int i = 0; i < 4; i++) {
            int idx = tid + i * 256, r = idx >> 3, c = idx & 7;
            int gr = row0 + r;
            cpa16(a_base + sw(r, c), A + (size_t)gr * K + c * 8, gr < N_NODES);
        }
        #pragma unroll
        for (int i = 0; i < 4; i++) {
            int idx = tid + i * 256, r = idx >> 3, c = idx & 7;
            cpa16(b_base + sw(r, c), Bt + (size_t)(col0 + r) * K + c * 8, true);
        }
        cpa_commit();
    }

    #pragma unroll
    for (int t = 0; t < KT; t++) {
        int buf = t & 1;
        if (t + 1 < KT) {
            int nb_ = (t + 1) & 1, kb = (t + 1) * 64;
            #pragma unroll
            for (int i = 0; i < 4; i++) {
                int idx = tid + i * 256, r = idx >> 3, c = idx & 7;
                int gr = row0 + r;
                cpa16(a_base + nb_ * 16384 + sw(r, c),
                      A + (size_t)gr * K + kb + c * 8, gr < N_NODES);
            }
            #pragma unroll
            for (int i = 0; i < 4; i++) {
                int idx = tid + i * 256, r = idx >> 3, c = idx & 7;
                cpa16(b_base + nb_ * 16384 + sw(r, c),
                      Bt + (size_t)(col0 + r) * K + kb + c * 8, true);
            }
            cpa_commit();
            cpa_wait<1>();
        } else {
            cpa_wait<0>();
        }
        __syncthreads();

        uint32_t ab = a_base + buf * 16384;
        uint32_t bb = b_base + buf * 16384;
        #pragma unroll
        for (int ks = 0; ks < 4; ks++) {
            int c0 = ks * 2;
            uint32_t af[4][4], bf[4][2];
            #pragma unroll
            for (int mt = 0; mt < 4; mt++) {
                int r = wm * 64 + mt * 16 + (lane & 15);
                int c = c0 + (lane >> 4);
                ldsm4(af[mt], ab + sw(r, c));
            }
            #pragma unroll
            for (int bg = 0; bg < 2; bg++) {
                int r = wn * 32 + bg * 16 + ((lane >> 4) << 3) + (lane & 7);
                int c = c0 + ((lane >> 3) & 1);
                uint32_t q[4];
                ldsm4(q, bb + sw(r, c));
                bf[bg * 2][0] = q[0]; bf[bg * 2][1] = q[1];
                bf[bg * 2 + 1][0] = q[2]; bf[bg * 2 + 1][1] = q[3];
            }
            #pragma unroll
            for (int mt = 0; mt < 4; mt++)
                #pragma unroll
                for (int nt = 0; nt < 4; nt++)
                    mma_f16(acc[mt][nt], af[mt], bf[nt]);
        }
        __syncthreads();
    }

    #pragma unroll
    for (int mt = 0; mt < 4; mt++) {
        #pragma unroll
        for (int h = 0; h < 2; h++) {
            int r = row0 + wm * 64 + mt * 16 + gid + h * 8;
            if (r < N_NODES) {
                #pragma unroll
                for (int nt = 0; nt < 4; nt++) {
                    int c = col0 + wn * 32 + nt * 8 + 2 * tig;
                    float v0 = acc[mt][nt][h * 2 + 0];
                    float v1 = acc[mt][nt][h * 2 + 1];
                    if (RELU) {
                        v0 = fmaxf(v0 + __ldg(&bias[c]), 0.f);
                        v1 = fmaxf(v1 + __ldg(&bias[c + 1]), 0.f);
                    }
                    *(__half2*)(C + (size_t)r * NTOT + c) = __floats2half2_rn(v0, v1);
                }
            }
        }
    }
}

__global__ __launch_bounds__(256) void k_gemm1(const float* __restrict__ b1) {
    gemm_body<128, 256, true>(g_agg, g_w1t, b1, g_h);
}
__global__ __launch_bounds__(256) void k_gemm2(const float* __restrict__ b2) {
    gemm_body<256, 256, true>(g_agg, g_w2t, b2, g_h);
}
__global__ __launch_bounds__(256) void k_gemm3() {
    gemm_body<256, 128, false>(g_h, g_w3t, nullptr, g_xw);
}

// ---------------- fused prep (single launch, serial stream) ------------------
#define XQ (N_NODES * D_IN / 4)
#define WT1 (D_HID * D_IN)
#define WT2 (D_HID * D_HID)
#define WT3 (D_OUT * D_HID)
#define PREP_TOTAL (N_EDGES + XQ + WT1 + WT2 + WT3)

__global__ void k_prep(const float* __restrict__ ew_raw,
                       const int* __restrict__ dst,
                       const float* __restrict__ x,
                       const float* __restrict__ W1,
                       const float* __restrict__ W2,
                       const float* __restrict__ W3) {
    int i = blockIdx.x * blockDim.x + threadIdx.x;
    if (i < N_EDGES) {
        float w = ew_raw[i];
        float sp = fmaxf(w, 0.0f) + log1pf(expf(-fabsf(w)));
        int d = dst[i];
        atomicAdd(&g_deg[d], sp);
        atomicAdd(&g_cnt[d], 1);
        return;
    }
    int j = i - N_EDGES;
    if (j < XQ) {
        float4 v = __ldg(&((const float4*)x)[j]);
        uint2 u;
        *(__half2*)&u.x = __floats2half2_rn(v.x, v.y);
        *(__half2*)&u.y = __floats2half2_rn(v.z, v.w);
        ((uint2*)g_xh)[j] = u;
        return;
    }
    j -= XQ;
    if (j < WT1) {
        int n = j / D_IN, k = j % D_IN;
        g_w1t[j] = __float2half_rn(W1[k * D_HID + n]);
        return;
    }
    j -= WT1;
    if (j < WT2) {
        int n = j / D_HID, k = j % D_HID;
        g_w2t[j] = __float2half_rn(W2[k * D_HID + n]);
        return;
    }
    j -= WT2;
    if (j < WT3) {
        int n = j / D_HID, k = j % D_HID;
        g_w3t[j] = __float2half_rn(W3[k * D_OUT + n]);
    }
}

// ---------------- scan -------------------------------------------------------
__global__ void k_scan() {
    __shared__ int s[SCAN_B];
    __shared__ bool isLast;
    int b = blockIdx.x, tid = threadIdx.x;
    int i = b * SCAN_B + tid;
    if (i < N_NODES) g_dinv[i] = rsqrtf(g_deg[i] + 1.0f);
    int v = (i < N_NODES) ? g_cnt[i] : 0;
    s[tid] = v;
    __syncthreads();
    #pragma unroll
    for (int off = 1; off < SCAN_B; off <<= 1) {
        int t = (tid >= off) ? s[tid - off] : 0;
        __syncthreads();
        s[tid] += t;
        __syncthreads();
    }
    int excl = s[tid] - v;
    if (i < N_NODES) { g_rowptr[i] = excl; g_fill[i] = excl; }
    if (i == N_NODES - 1) g_rowptr[N_NODES] = s[tid];
    if (tid == SCAN_B - 1) g_part[b] = s[tid];

    __threadfence();
    __syncthreads();
    if (tid == 0) isLast = (atomicAdd(&g_tick, 1) == NCHUNK - 1);
    __syncthreads();
    if (!isLast) return;
    __threadfence();

    int v2 = (tid < NCHUNK) ? g_part[tid] : 0;
    s[tid] = (tid < 64) ? v2 : 0;
    __syncthreads();
    #pragma unroll
    for (int off = 1; off < 64; off <<= 1) {
        int t = (tid >= off && tid < 64) ? s[tid - off] : 0;
        __syncthreads();
        if (tid < 64) s[tid] += t;
        __syncthreads();
    }
    if (tid < NCHUNK) g_partscan[tid] = s[tid] - v2;
    if (tid == 0) g_tick = 0;
}

// ---------------- place: recompute softplus, pack int2, deferred reset -------
__global__ void k_place(const float* __restrict__ ew_raw,
                        const int* __restrict__ src,
                        const int* __restrict__ dst) {
    int i = blockIdx.x * blockDim.x + threadIdx.x;
    if (i < N_EDGES) {
        float rw = ew_raw[i];
        float sp = fmaxf(rw, 0.0f) + log1pf(expf(-fabsf(rw)));
        int s = src[i], d = dst[i];
        float w = g_dinv[s] * sp * g_dinv[d];
        unsigned int hw = (unsigned int)__half_as_ushort(__float2half_rn(w));
        int pos = atomicAdd(&g_fill[d], 1) + g_partscan[d >> 10];
        g_csr[pos] = make_int2(s, (int)(hw | (hw << 16)));
    }
    if (i < N_NODES) { g_deg[i] = 0.0f; g_cnt[i] = 0; }
}

// ---------------- aggregation: 8-edge MLP groups, int2 CSR -------------------
template <int DIM, bool OUT_FLOAT>
__device__ __forceinline__ void agg_half_body(const __half* __restrict__ src,
                                              __half* __restrict__ dsth,
                                              float* __restrict__ dstf,
                                              const float* __restrict__ bias) {
    int warp = (blockIdx.x * blockDim.x + threadIdx.x) >> 5;
    int lane = threadIdx.x & 31;
    if (warp >= N_NODES) return;
    constexpr int V = DIM / 128;

    int start = g_rowptr[warp] + g_partscan[warp >> 10];
    int end   = g_rowptr[warp + 1] + g_partscan[(warp + 1) >> 10];
    float di = g_dinv[warp];
    float w0 = di * di;

    float2 acc[2 * V];
    {
        if (V == 1) {
            uint2 u = __ldg(&((const uint2*)(src + (size_t)warp * DIM))[lane]);
            float2 f0 = __half22float2(u2h2(u.x)), f1 = __half22float2(u2h2(u.y));
            acc[0] = make_float2(w0 * f0.x, w0 * f0.y);
            acc[1] = make_float2(w0 * f1.x, w0 * f1.y);
        } else {
            uint4 u = __ldg(&((const uint4*)(src + (size_t)warp * DIM))[lane]);
            float2 f0 = __half22float2(u2h2(u.x)), f1 = __half22float2(u2h2(u.y));
            float2 f2 = __half22float2(u2h2(u.z)), f3 = __half22float2(u2h2(u.w));
            acc[0] = make_float2(w0 * f0.x, w0 * f0.y);
            acc[1] = make_float2(w0 * f1.x, w0 * f1.y);
            acc[2] = make_float2(w0 * f2.x, w0 * f2.y);
            acc[3] = make_float2(w0 * f3.x, w0 * f3.y);
        }
    }

    int e = start;
    for (; e + 7 < end; e += 8) {
        int2 ce[8];
        #pragma unroll
        for (int q = 0; q < 8; q++) ce[q] = g_csr[e + q];
        if (V == 1) {
            uint2 a[8];
            #pragma unroll
            for (int q = 0; q < 8; q++)
                a[q] = __ldg(&((const uint2*)(src + (size_t)ce[q].x * DIM))[lane]);
            #pragma unroll
            for (int g2 = 0; g2 < 2; g2++) {
                int o = g2 * 4;
                __half2 h0 = __hmul2(u2h2(a[o].x), u2h2((unsigned)ce[o].y));
                __half2 h1 = __hmul2(u2h2(a[o].y), u2h2((unsigned)ce[o].y));
                #pragma unroll
                for (int q = 1; q < 4; q++) {
                    __half2 wq = u2h2((unsigned)ce[o + q].y);
                    h0 = __hfma2(u2h2(a[o + q].x), wq, h0);
                    h1 = __hfma2(u2h2(a[o + q].y), wq, h1);
                }
                float2 f0 = __half22float2(h0), f1 = __half22float2(h1);
                acc[0].x += f0.x; acc[0].y += f0.y;
                acc[1].x += f1.x; acc[1].y += f1.y;
            }
        } else {
            uint4 a[8];
            #pragma unroll
            for (int q = 0; q < 8; q++)
                a[q] = __ldg(&((const uint4*)(src + (size_t)ce[q].x * DIM))[lane]);
            #pragma unroll
            for (int g2 = 0; g2 < 2; g2++) {
                int o = g2 * 4;
                __half2 w_ = u2h2((unsigned)ce[o].y);
                __half2 h0 = __hmul2(u2h2(a[o].x), w_);
                __half2 h1 = __hmul2(u2h2(a[o].y), w_);
                __half2 h2 = __hmul2(u2h2(a[o].z), w_);
                __half2 h3 = __hmul2(u2h2(a[o].w), w_);
                #pragma unroll
                for (int q = 1; q < 4; q++) {
                    __half2 wq = u2h2((unsigned)ce[o + q].y);
                    h0 = __hfma2(u2h2(a[o + q].x), wq, h0);
                    h1 = __hfma2(u2h2(a[o + q].y), wq, h1);
                    h2 = __hfma2(u2h2(a[o + q].z), wq, h2);
                    h3 = __hfma2(u2h2(a[o + q].w), wq, h3);
                }
                float2 f0 = __half22float2(h0), f1 = __half22float2(h1);
                float2 f2 = __half22float2(h2), f3 = __half22float2(h3);
                acc[0].x += f0.x; acc[0].y += f0.y;
                acc[1].x += f1.x; acc[1].y += f1.y;
                acc[2].x += f2.x; acc[2].y += f2.y;
                acc[3].x += f3.x; acc[3].y += f3.y;
            }
        }
    }
    for (; e + 3 < end; e += 4) {
        int2 ce[4];
        #pragma unroll
        for (int q = 0; q < 4; q++) ce[q] = g_csr[e + q];
        if (V == 1) {
            uint2 a[4];
            #pragma unroll
            for (int q = 0; q < 4; q++)
                a[q] = __ldg(&((const uint2*)(src + (size_t)ce[q].x * DIM))[lane]);
            __half2 h0 = __hmul2(u2h2(a[0].x), u2h2((unsigned)ce[0].y));
            __half2 h1 = __hmul2(u2h2(a[0].y), u2h2((unsigned)ce[0].y));
            #pragma unroll
            for (int q = 1; q < 4; q++) {
                __half2 wq = u2h2((unsigned)ce[q].y);
                h0 = __hfma2(u2h2(a[q].x), wq, h0);
                h1 = __hfma2(u2h2(a[q].y), wq, h1);
            }
            float2 f0 = __half22float2(h0), f1 = __half22float2(h1);
            acc[0].x += f0.x; acc[0].y += f0.y;
            acc[1].x += f1.x; acc[1].y += f1.y;
        } else {
            uint4 a[4];
            #pragma unroll
            for (int q = 0; q < 4; q++)
                a[q] = __ldg(&((const uint4*)(src + (size_t)ce[q].x * DIM))[lane]);
            __half2 w_ = u2h2((unsigned)ce[0].y);
            __half2 h0 = __hmul2(u2h2(a[0].x), w_);
            __half2 h1 = __hmul2(u2h2(a[0].y), w_);
            __half2 h2 = __hmul2(u2h2(a[0].z), w_);
            __half2 h3 = __hmul2(u2h2(a[0].w), w_);
            #pragma unroll
            for (int q = 1; q < 4; q++) {
                __half2 wq = u2h2((unsigned)ce[q].y);
                h0 = __hfma2(u2h2(a[q].x), wq, h0);
                h1 = __hfma2(u2h2(a[q].y), wq, h1);
                h2 = __hfma2(u2h2(a[q].z), wq, h2);
                h3 = __hfma2(u2h2(a[q].w), wq, h3);
            }
            float2 f0 = __half22float2(h0), f1 = __half22float2(h1);
            float2 f2 = __half22float2(h2), f3 = __half22float2(h3);
            acc[0].x += f0.x; acc[0].y += f0.y;
            acc[1].x += f1.x; acc[1].y += f1.y;
            acc[2].x += f2.x; acc[2].y += f2.y;
            acc[3].x += f3.x; acc[3].y += f3.y;
        }
    }
    for (; e < end; e++) {
        int2 ce = g_csr[e];
        float w1 = __half2float(__low2half(u2h2((unsigned)ce.y)));
        if (V == 1) {
            uint2 a = __ldg(&((const uint2*)(src + (size_t)ce.x * DIM))[lane]);
            float2 f0 = __half22float2(u2h2(a.x)), f1 = __half22float2(u2h2(a.y));
            acc[0].x += w1 * f0.x; acc[0].y += w1 * f0.y;
            acc[1].x += w1 * f1.x; acc[1].y += w1 * f1.y;
        } else {
            uint4 a = __ldg(&((const uint4*)(src + (size_t)ce.x * DIM))[lane]);
            float2 f0 = __half22float2(u2h2(a.x)), f1 = __half22float2(u2h2(a.y));
            float2 f2 = __half22float2(u2h2(a.z)), f3 = __half22float2(u2h2(a.w));
            acc[0].x += w1 * f0.x; acc[0].y += w1 * f0.y;
            acc[1].x += w1 * f1.x; acc[1].y += w1 * f1.y;
            acc[2].x += w1 * f2.x; acc[2].y += w1 * f2.y;
            acc[3].x += w1 * f3.x; acc[3].y += w1 * f3.y;
        }
    }

    if (OUT_FLOAT) {
        float4 b4 = __ldg(&((const float4*)bias)[lane]);
        ((float4*)(dstf + (size_t)warp * DIM))[lane] =
            make_float4(acc[0].x + b4.x, acc[0].y + b4.y,
                        acc[1].x + b4.z, acc[1].y + b4.w);
    } else {
        if (V == 1) {
            uint2 u;
            *(__half2*)&u.x = __floats2half2_rn(acc[0].x, acc[0].y);
            *(__half2*)&u.y = __floats2half2_rn(acc[1].x, acc[1].y);
            ((uint2*)(dsth + (size_t)warp * DIM))[lane] = u;
        } else {
            uint4 u;
            *(__half2*)&u.x = __floats2half2_rn(acc[0].x, acc[0].y);
            *(__half2*)&u.y = __floats2half2_rn(acc[1].x, acc[1].y);
            *(__half2*)&u.z = __floats2half2_rn(acc[2].x, acc[2].y);
            *(__half2*)&u.w = __floats2half2_rn(acc[3].x, acc[3].y);
            ((uint4*)(dsth + (size_t)warp * DIM))[lane] = u;
        }
    }
}

__global__ void k_agg_x() {
    agg_half_body<128, false>(g_xh, g_agg, nullptr, nullptr);
}
__global__ void k_agg_h() {
    agg_half_body<256, false>(g_h, g_agg, nullptr, nullptr);
}
__global__ void k_agg_out(float* __restrict__ out, const float* __restrict__ b3) {
    agg_half_body<128, true>(g_xw, nullptr, out, b3);
}

// ---------------- launch -----------------------------------------------------
extern "C" void kernel_launch(void* const* d_in, const int* in_sizes, int n_in,
                              void* d_out, int out_size) {
    const float* x      = (const float*)d_in[0];
    const int*   ei     = (const int*)d_in[1];   // int32 (harness downcasts int64)
    const float* ew_raw = (const float*)d_in[2];
    const float* W1     = (const float*)d_in[3];
    const float* b1     = (const float*)d_in[4];
    const float* W2     = (const float*)d_in[5];
    const float* b2     = (const float*)d_in[6];
    const float* W3     = (const float*)d_in[7];
    const float* b3     = (const float*)d_in[8];
    float* out          = (float*)d_out;

    const int* src = ei;
    const int* dst = ei + N_EDGES;

    const int T = 256;
    int nb_edges = (N_EDGES + T - 1) / T;
    int agg_blocks = (N_NODES * 32 + T - 1) / T;
    int gm = (N_NODES + 127) / 128;   // 391

    const int GEMM_SMEM = 65536;
    cudaFuncSetAttribute(k_gemm1, cudaFuncAttributeMaxDynamicSharedMemorySize, GEMM_SMEM);
    cudaFuncSetAttribute(k_gemm2, cudaFuncAttributeMaxDynamicSharedMemorySize, GEMM_SMEM);
    cudaFuncSetAttribute(k_gemm3, cudaFuncAttributeMaxDynamicSharedMemorySize, GEMM_SMEM);

    // serial, single stream (R14's fork regressed: both sides memory-bound)
    k_prep<<<(PREP_TOTAL + T - 1) / T, T>>>(ew_raw, dst, x, W1, W2, W3);
    k_scan<<<NCHUNK, SCAN_B>>>();
    k_place<<<nb_edges, T>>>(ew_raw, src, dst);

    k_agg_x<<<agg_blocks, T>>>();
    k_gemm1<<<dim3(gm, 2), 256, GEMM_SMEM>>>(b1);

    k_agg_h<<<agg_blocks, T>>>();
    k_gemm2<<<dim3(gm, 2), 256, GEMM_SMEM>>>(b2);

    k_gemm3<<<dim3(gm, 1), 256, GEMM_SMEM>>>();
    k_agg_out<<<agg_blocks, T>>>(out, b3);
}

// round 17
// speedup vs baseline: 1.0791x; 1.0549x over previous
#include <cuda_runtime.h>
#include <cuda_fp16.h>
#include <cstdint>

#define N_NODES 50000
#define N_EDGES 600000
#define D_IN 128
#define D_HID 256
#define D_OUT 128
#define SCAN_B 1024
#define NCHUNK ((N_NODES + SCAN_B - 1) / SCAN_B)   // 49

// ---------------- scratch (device globals; bound ONLY in device code) --------
__device__ float g_deg[N_NODES];
__device__ float g_dinv[N_NODES];
__device__ int   g_cnt[N_NODES];
__device__ int   g_rowptr[N_NODES + 1];
__device__ int   g_fill[N_NODES];
__device__ int   g_part[NCHUNK];
__device__ int   g_partscan[NCHUNK];
__device__ int   g_tick;
__device__ int   g_csr_src[N_EDGES];
__device__ unsigned int g_csr_wh[N_EDGES];   // packed half2 {w,w}
__device__ __align__(256) __half g_xh[N_NODES * D_IN];
__device__ __align__(256) __half g_agg[N_NODES * D_HID];
__device__ __align__(256) __half g_h[N_NODES * D_HID];
__device__ __align__(256) __half g_xw[N_NODES * D_OUT];
__device__ __align__(256) __half g_w1t[D_HID * D_IN];
__device__ __align__(256) __half g_w2t[D_HID * D_HID];
__device__ __align__(256) __half g_w3t[D_OUT * D_HID];

// ---------------- asm helpers ------------------------------------------------
__device__ __forceinline__ uint32_t smem_u32(const void* p) {
    uint32_t a;
    asm("{ .reg .u64 t; cvta.to.shared.u64 t, %1; cvt.u32.u64 %0, t; }"
        : "=r"(a) : "l"(p));
    return a;
}
__device__ __forceinline__ void ldsm4(uint32_t* r, uint32_t addr) {
    asm volatile("ldmatrix.sync.aligned.m8n8.x4.shared.b16 {%0,%1,%2,%3}, [%4];"
                 : "=r"(r[0]), "=r"(r[1]), "=r"(r[2]), "=r"(r[3]) : "r"(addr));
}
__device__ __forceinline__ void cpa16(uint32_t saddr, const void* g, bool pred) {
    int sz = pred ? 16 : 0;
    asm volatile("cp.async.ca.shared.global [%0], [%1], 16, %2;"
                 :: "r"(saddr), "l"(g), "r"(sz));
}
__device__ __forceinline__ void cpa_commit() {
    asm volatile("cp.async.commit_group;" ::: "memory");
}
template <int N>
__device__ __forceinline__ void cpa_wait() {
    asm volatile("cp.async.wait_group %0;" :: "n"(N) : "memory");
}
__device__ __forceinline__ void mma_f16(float* c, const uint32_t* a, const uint32_t* b) {
    asm volatile(
        "mma.sync.aligned.m16n8k16.row.col.f32.f16.f16.f32 "
        "{%0,%1,%2,%3}, {%4,%5,%6,%7}, {%8,%9}, {%0,%1,%2,%3};\n"
        : "+f"(c[0]), "+f"(c[1]), "+f"(c[2]), "+f"(c[3])
        : "r"(a[0]), "r"(a[1]), "r"(a[2]), "r"(a[3]), "r"(b[0]), "r"(b[1]));
}
__device__ __forceinline__ uint32_t sw(int r, int c) {
    return (uint32_t)r * 128u + (uint32_t)((c ^ (r & 7)) << 4);
}
__device__ __forceinline__ __half2 u2h2(unsigned int u) {
    __half2 h; *(unsigned int*)&h = u; return h;
}

// ---------------- GEMM body (unchanged; at legacy-HMMA ceiling) --------------
template <int K, int NTOT, bool RELU>
__device__ __forceinline__ void gemm_body(const __half* __restrict__ A,
                                          const __half* __restrict__ Bt,
                                          const float* __restrict__ bias,
                                          __half* __restrict__ C) {
    extern __shared__ __align__(16) char dsm[];
    uint32_t a_base = smem_u32(dsm);
    uint32_t b_base = a_base + 32768;

    int tid = threadIdx.x;
    int lane = tid & 31, warp = tid >> 5;
    int gid = lane >> 2, tig = lane & 3;
    int wm = warp >> 2, wn = warp & 3;
    int row0 = blockIdx.x * 128;
    int col0 = blockIdx.y * 128;

    float acc[4][4][4];
    #pragma unroll
    for (int mt = 0; mt < 4; mt++)
        #pragma unroll
        for (int nt = 0; nt < 4; nt++)
            #pragma unroll
            for (int q = 0; q < 4; q++) acc[mt][nt][q] = 0.f;

    constexpr int KT = K / 64;

    {
        #pragma unroll
        for (int i = 0; i < 4; i++) {
            int idx = tid + i * 256, r = idx >> 3, c = idx & 7;
            int gr = row0 + r;
            cpa16(a_base + sw(r, c), A + (size_t)gr * K + c * 8, gr < N_NODES);
        }
        #pragma unroll
        for (int i = 0; i < 4; i++) {
            int idx = tid + i * 256, r = idx >> 3, c = idx & 7;
            cpa16(b_base + sw(r, c), Bt + (size_t)(col0 + r) * K + c * 8, true);
        }
        cpa_commit();
    }

    #pragma unroll
    for (int t = 0; t < KT; t++) {
        int buf = t & 1;
        if (t + 1 < KT) {
            int nb_ = (t + 1) & 1, kb = (t + 1) * 64;
            #pragma unroll
            for (int i = 0; i < 4; i++) {
                int idx = tid + i * 256, r = idx >> 3, c = idx & 7;
                int gr = row0 + r;
                cpa16(a_base + nb_ * 16384 + sw(r, c),
                      A + (size_t)gr * K + kb + c * 8, gr < N_NODES);
            }
            #pragma unroll
            for (int i = 0; i < 4; i++) {
                int idx = tid + i * 256, r = idx >> 3, c = idx & 7;
                cpa16(b_base + nb_ * 16384 + sw(r, c),
                      Bt + (size_t)(col0 + r) * K + kb + c * 8, true);
            }
            cpa_commit();
            cpa_wait<1>();
        } else {
            cpa_wait<0>();
        }
        __syncthreads();

        uint32_t ab = a_base + buf * 16384;
        uint32_t bb = b_base + buf * 16384;
        #pragma unroll
        for (int ks = 0; ks < 4; ks++) {
            int c0 = ks * 2;
            uint32_t af[4][4], bf[4][2];
            #pragma unroll
            for (int mt = 0; mt < 4; mt++) {
                int r = wm * 64 + mt * 16 + (lane & 15);
                int c = c0 + (lane >> 4);
                ldsm4(af[mt], ab + sw(r, c));
            }
            #pragma unroll
            for (int bg = 0; bg < 2; bg++) {
                int r = wn * 32 + bg * 16 + ((lane >> 4) << 3) + (lane & 7);
                int c = c0 + ((lane >> 3) & 1);
                uint32_t q[4];
                ldsm4(q, bb + sw(r, c));
                bf[bg * 2][0] = q[0]; bf[bg * 2][1] = q[1];
                bf[bg * 2 + 1][0] = q[2]; bf[bg * 2 + 1][1] = q[3];
            }
            #pragma unroll
            for (int mt = 0; mt < 4; mt++)
                #pragma unroll
                for (int nt = 0; nt < 4; nt++)
                    mma_f16(acc[mt][nt], af[mt], bf[nt]);
        }
        __syncthreads();
    }

    #pragma unroll
    for (int mt = 0; mt < 4; mt++) {
        #pragma unroll
        for (int h = 0; h < 2; h++) {
            int r = row0 + wm * 64 + mt * 16 + gid + h * 8;
            if (r < N_NODES) {
                #pragma unroll
                for (int nt = 0; nt < 4; nt++) {
                    int c = col0 + wn * 32 + nt * 8 + 2 * tig;
                    float v0 = acc[mt][nt][h * 2 + 0];
                    float v1 = acc[mt][nt][h * 2 + 1];
                    if (RELU) {
                        v0 = fmaxf(v0 + __ldg(&bias[c]), 0.f);
                        v1 = fmaxf(v1 + __ldg(&bias[c + 1]), 0.f);
                    }
                    *(__half2*)(C + (size_t)r * NTOT + c) = __floats2half2_rn(v0, v1);
                }
            }
        }
    }
}

__global__ __launch_bounds__(256) void k_gemm1(const float* __restrict__ b1) {
    gemm_body<128, 256, true>(g_agg, g_w1t, b1, g_h);
}
__global__ __launch_bounds__(256) void k_gemm2(const float* __restrict__ b2) {
    gemm_body<256, 256, true>(g_agg, g_w2t, b2, g_h);
}
__global__ __launch_bounds__(256) void k_gemm3() {
    gemm_body<256, 128, false>(g_h, g_w3t, nullptr, g_xw);
}

// ---------------- fused prep (single launch; no g_ew write) ------------------
#define XQ (N_NODES * D_IN / 4)
#define WT1 (D_HID * D_IN)
#define WT2 (D_HID * D_HID)
#define WT3 (D_OUT * D_HID)
#define PREP_TOTAL (N_EDGES + XQ + WT1 + WT2 + WT3)

__global__ void k_prep(const float* __restrict__ ew_raw,
                       const int* __restrict__ dst,
                       const float* __restrict__ x,
                       const float* __restrict__ W1,
                       const float* __restrict__ W2,
                       const float* __restrict__ W3) {
    int i = blockIdx.x * blockDim.x + threadIdx.x;
    if (i < N_EDGES) {
        float w = ew_raw[i];
        float sp = fmaxf(w, 0.0f) + log1pf(expf(-fabsf(w)));
        int d = dst[i];
        atomicAdd(&g_deg[d], sp);
        atomicAdd(&g_cnt[d], 1);
        return;
    }
    int j = i - N_EDGES;
    if (j < XQ) {
        float4 v = __ldg(&((const float4*)x)[j]);
        uint2 u;
        *(__half2*)&u.x = __floats2half2_rn(v.x, v.y);
        *(__half2*)&u.y = __floats2half2_rn(v.z, v.w);
        ((uint2*)g_xh)[j] = u;
        return;
    }
    j -= XQ;
    if (j < WT1) {
        int n = j / D_IN, k = j % D_IN;
        g_w1t[j] = __float2half_rn(W1[k * D_HID + n]);
        return;
    }
    j -= WT1;
    if (j < WT2) {
        int n = j / D_HID, k = j % D_HID;
        g_w2t[j] = __float2half_rn(W2[k * D_HID + n]);
        return;
    }
    j -= WT2;
    if (j < WT3) {
        int n = j / D_HID, k = j % D_HID;
        g_w3t[j] = __float2half_rn(W3[k * D_OUT + n]);
    }
}

// ---------------- scan -------------------------------------------------------
__global__ void k_scan() {
    __shared__ int s[SCAN_B];
    __shared__ bool isLast;
    int b = blockIdx.x, tid = threadIdx.x;
    int i = b * SCAN_B + tid;
    if (i < N_NODES) g_dinv[i] = rsqrtf(g_deg[i] + 1.0f);
    int v = (i < N_NODES) ? g_cnt[i] : 0;
    s[tid] = v;
    __syncthreads();
    #pragma unroll
    for (int off = 1; off < SCAN_B; off <<= 1) {
        int t = (tid >= off) ? s[tid - off] : 0;
        __syncthreads();
        s[tid] += t;
        __syncthreads();
    }
    int excl = s[tid] - v;
    if (i < N_NODES) { g_rowptr[i] = excl; g_fill[i] = excl; }
    if (i == N_NODES - 1) g_rowptr[N_NODES] = s[tid];
    if (tid == SCAN_B - 1) g_part[b] = s[tid];

    __threadfence();
    __syncthreads();
    if (tid == 0) isLast = (atomicAdd(&g_tick, 1) == NCHUNK - 1);
    __syncthreads();
    if (!isLast) return;
    __threadfence();

    int v2 = (tid < NCHUNK) ? g_part[tid] : 0;
    s[tid] = (tid < 64) ? v2 : 0;
    __syncthreads();
    #pragma unroll
    for (int off = 1; off < 64; off <<= 1) {
        int t = (tid >= off && tid < 64) ? s[tid - off] : 0;
        __syncthreads();
        if (tid < 64) s[tid] += t;
        __syncthreads();
    }
    if (tid < NCHUNK) g_partscan[tid] = s[tid] - v2;
    if (tid == 0) g_tick = 0;
}

// ---------------- place: recompute softplus; separate CSR arrays -------------
__global__ void k_place(const float* __restrict__ ew_raw,
                        const int* __restrict__ src,
                        const int* __restrict__ dst) {
    int i = blockIdx.x * blockDim.x + threadIdx.x;
    if (i < N_EDGES) {
        float rw = ew_raw[i];
        float sp = fmaxf(rw, 0.0f) + log1pf(expf(-fabsf(rw)));
        int s = src[i], d = dst[i];
        float w = g_dinv[s] * sp * g_dinv[d];
        unsigned int hw = (unsigned int)__half_as_ushort(__float2half_rn(w));
        int pos = atomicAdd(&g_fill[d], 1) + g_partscan[d >> 10];
        g_csr_src[pos] = s;
        g_csr_wh[pos] = hw | (hw << 16);
    }
    if (i < N_NODES) { g_deg[i] = 0.0f; g_cnt[i] = 0; }
}

// ---------------- aggregation: R13-exact (8-edge MLP groups, regs=32) --------
template <int DIM, bool OUT_FLOAT>
__device__ __forceinline__ void agg_half_body(const __half* __restrict__ src,
                                              __half* __restrict__ dsth,
                                              float* __restrict__ dstf,
                                              const float* __restrict__ bias) {
    int warp = (blockIdx.x * blockDim.x + threadIdx.x) >> 5;
    int lane = threadIdx.x & 31;
    if (warp >= N_NODES) return;
    constexpr int V = DIM / 128;   // 1: uint2/lane; 2: uint4/lane

    int start = g_rowptr[warp] + g_partscan[warp >> 10];
    int end   = g_rowptr[warp + 1] + g_partscan[(warp + 1) >> 10];
    float di = g_dinv[warp];
    float w0 = di * di;

    float2 acc[2 * V];
    {
        if (V == 1) {
            uint2 u = __ldg(&((const uint2*)(src + (size_t)warp * DIM))[lane]);
            float2 f0 = __half22float2(u2h2(u.x)), f1 = __half22float2(u2h2(u.y));
            acc[0] = make_float2(w0 * f0.x, w0 * f0.y);
            acc[1] = make_float2(w0 * f1.x, w0 * f1.y);
        } else {
            uint4 u = __ldg(&((const uint4*)(src + (size_t)warp * DIM))[lane]);
            float2 f0 = __half22float2(u2h2(u.x)), f1 = __half22float2(u2h2(u.y));
            float2 f2 = __half22float2(u2h2(u.z)), f3 = __half22float2(u2h2(u.w));
            acc[0] = make_float2(w0 * f0.x, w0 * f0.y);
            acc[1] = make_float2(w0 * f1.x, w0 * f1.y);
            acc[2] = make_float2(w0 * f2.x, w0 * f2.y);
            acc[3] = make_float2(w0 * f3.x, w0 * f3.y);
        }
    }

    int e = start;
    // ---- 8-edge groups: all 8 row loads issued up front (MLP=8) ----
    for (; e + 7 < end; e += 8) {
        int sidx[8];
        __half2 wh[8];
        #pragma unroll
        for (int q = 0; q < 8; q++) {
            sidx[q] = g_csr_src[e + q];
            wh[q] = u2h2(g_csr_wh[e + q]);
        }
        if (V == 1) {
            uint2 a[8];
            #pragma unroll
            for (int q = 0; q < 8; q++)
                a[q] = __ldg(&((const uint2*)(src + (size_t)sidx[q] * DIM))[lane]);
            #pragma unroll
            for (int g2 = 0; g2 < 2; g2++) {
                int o = g2 * 4;
                __half2 h0 = __hmul2(u2h2(a[o].x), wh[o]);
                __half2 h1 = __hmul2(u2h2(a[o].y), wh[o]);
                #pragma unroll
                for (int q = 1; q < 4; q++) {
                    h0 = __hfma2(u2h2(a[o + q].x), wh[o + q], h0);
                    h1 = __hfma2(u2h2(a[o + q].y), wh[o + q], h1);
                }
                float2 f0 = __half22float2(h0), f1 = __half22float2(h1);
                acc[0].x += f0.x; acc[0].y += f0.y;
                acc[1].x += f1.x; acc[1].y += f1.y;
            }
        } else {
            uint4 a[8];
            #pragma unroll
            for (int q = 0; q < 8; q++)
                a[q] = __ldg(&((const uint4*)(src + (size_t)sidx[q] * DIM))[lane]);
            #pragma unroll
            for (int g2 = 0; g2 < 2; g2++) {
                int o = g2 * 4;
                __half2 h0 = __hmul2(u2h2(a[o].x), wh[o]);
                __half2 h1 = __hmul2(u2h2(a[o].y), wh[o]);
                __half2 h2 = __hmul2(u2h2(a[o].z), wh[o]);
                __half2 h3 = __hmul2(u2h2(a[o].w), wh[o]);
                #pragma unroll
                for (int q = 1; q < 4; q++) {
                    h0 = __hfma2(u2h2(a[o + q].x), wh[o + q], h0);
                    h1 = __hfma2(u2h2(a[o + q].y), wh[o + q], h1);
                    h2 = __hfma2(u2h2(a[o + q].z), wh[o + q], h2);
                    h3 = __hfma2(u2h2(a[o + q].w), wh[o + q], h3);
                }
                float2 f0 = __half22float2(h0), f1 = __half22float2(h1);
                float2 f2 = __half22float2(h2), f3 = __half22float2(h3);
                acc[0].x += f0.x; acc[0].y += f0.y;
                acc[1].x += f1.x; acc[1].y += f1.y;
                acc[2].x += f2.x; acc[2].y += f2.y;
                acc[3].x += f3.x; acc[3].y += f3.y;
            }
        }
    }
    // ---- 4-edge group ----
    for (; e + 3 < end; e += 4) {
        int sidx[4];
        __half2 wh[4];
        #pragma unroll
        for (int q = 0; q < 4; q++) {
            sidx[q] = g_csr_src[e + q];
            wh[q] = u2h2(g_csr_wh[e + q]);
        }
        if (V == 1) {
            uint2 a[4];
            #pragma unroll
            for (int q = 0; q < 4; q++)
                a[q] = __ldg(&((const uint2*)(src + (size_t)sidx[q] * DIM))[lane]);
            __half2 h0 = __hmul2(u2h2(a[0].x), wh[0]);
            __half2 h1 = __hmul2(u2h2(a[0].y), wh[0]);
            #pragma unroll
            for (int q = 1; q < 4; q++) {
                h0 = __hfma2(u2h2(a[q].x), wh[q], h0);
                h1 = __hfma2(u2h2(a[q].y), wh[q], h1);
            }
            float2 f0 = __half22float2(h0), f1 = __half22float2(h1);
            acc[0].x += f0.x; acc[0].y += f0.y;
            acc[1].x += f1.x; acc[1].y += f1.y;
        } else {
            uint4 a[4];
            #pragma unroll
            for (int q = 0; q < 4; q++)
                a[q] = __ldg(&((const uint4*)(src + (size_t)sidx[q] * DIM))[lane]);
            __half2 h0 = __hmul2(u2h2(a[0].x), wh[0]);
            __half2 h1 = __hmul2(u2h2(a[0].y), wh[0]);
            __half2 h2 = __hmul2(u2h2(a[0].z), wh[0]);
            __half2 h3 = __hmul2(u2h2(a[0].w), wh[0]);
            #pragma unroll
            for (int q = 1; q < 4; q++) {
                h0 = __hfma2(u2h2(a[q].x), wh[q], h0);
                h1 = __hfma2(u2h2(a[q].y), wh[q], h1);
                h2 = __hfma2(u2h2(a[q].z), wh[q], h2);
                h3 = __hfma2(u2h2(a[q].w), wh[q], h3);
            }
            float2 f0 = __half22float2(h0), f1 = __half22float2(h1);
            float2 f2 = __half22float2(h2), f3 = __half22float2(h3);
            acc[0].x += f0.x; acc[0].y += f0.y;
            acc[1].x += f1.x; acc[1].y += f1.y;
            acc[2].x += f2.x; acc[2].y += f2.y;
            acc[3].x += f3.x; acc[3].y += f3.y;
        }
    }
    // ---- scalar tail ----
    for (; e < end; e++) {
        int s0 = g_csr_src[e];
        float w1 = __half2float(__low2half(u2h2(g_csr_wh[e])));
        if (V == 1) {
            uint2 a = __ldg(&((const uint2*)(src + (size_t)s0 * DIM))[lane]);
            float2 f0 = __half22float2(u2h2(a.x)), f1 = __half22float2(u2h2(a.y));
            acc[0].x += w1 * f0.x; acc[0].y += w1 * f0.y;
            acc[1].x += w1 * f1.x; acc[1].y += w1 * f1.y;
        } else {
            uint4 a = __ldg(&((const uint4*)(src + (size_t)s0 * DIM))[lane]);
            float2 f0 = __half22float2(u2h2(a.x)), f1 = __half22float2(u2h2(a.y));
            float2 f2 = __half22float2(u2h2(a.z)), f3 = __half22float2(u2h2(a.w));
            acc[0].x += w1 * f0.x; acc[0].y += w1 * f0.y;
            acc[1].x += w1 * f1.x; acc[1].y += w1 * f1.y;
            acc[2].x += w1 * f2.x; acc[2].y += w1 * f2.y;
            acc[3].x += w1 * f3.x; acc[3].y += w1 * f3.y;
        }
    }

    if (OUT_FLOAT) {   // DIM=128 only
        float4 b4 = __ldg(&((const float4*)bias)[lane]);
        ((float4*)(dstf + (size_t)warp * DIM))[lane] =
            make_float4(acc[0].x + b4.x, acc[0].y + b4.y,
                        acc[1].x + b4.z, acc[1].y + b4.w);
    } else {
        if (V == 1) {
            uint2 u;
            *(__half2*)&u.x = __floats2half2_rn(acc[0].x, acc[0].y);
            *(__half2*)&u.y = __floats2half2_rn(acc[1].x, acc[1].y);
            ((uint2*)(dsth + (size_t)warp * DIM))[lane] = u;
        } else {
            uint4 u;
            *(__half2*)&u.x = __floats2half2_rn(acc[0].x, acc[0].y);
            *(__half2*)&u.y = __floats2half2_rn(acc[1].x, acc[1].y);
            *(__half2*)&u.z = __floats2half2_rn(acc[2].x, acc[2].y);
            *(__half2*)&u.w = __floats2half2_rn(acc[3].x, acc[3].y);
            ((uint4*)(dsth + (size_t)warp * DIM))[lane] = u;
        }
    }
}

__global__ void k_agg_x() {
    agg_half_body<128, false>(g_xh, g_agg, nullptr, nullptr);
}
__global__ void k_agg_h() {
    agg_half_body<256, false>(g_h, g_agg, nullptr, nullptr);
}
__global__ void k_agg_out(float* __restrict__ out, const float* __restrict__ b3) {
    agg_half_body<128, true>(g_xw, nullptr, out, b3);
}

// ---------------- launch -----------------------------------------------------
extern "C" void kernel_launch(void* const* d_in, const int* in_sizes, int n_in,
                              void* d_out, int out_size) {
    const float* x      = (const float*)d_in[0];
    const int*   ei     = (const int*)d_in[1];   // int32 (harness downcasts int64)
    const float* ew_raw = (const float*)d_in[2];
    const float* W1     = (const float*)d_in[3];
    const float* b1     = (const float*)d_in[4];
    const float* W2     = (const float*)d_in[5];
    const float* b2     = (const float*)d_in[6];
    const float* W3     = (const float*)d_in[7];
    const float* b3     = (const float*)d_in[8];
    float* out          = (float*)d_out;

    const int* src = ei;
    const int* dst = ei + N_EDGES;

    const int T = 256;
    int nb_edges = (N_EDGES + T - 1) / T;
    int agg_blocks = (N_NODES * 32 + T - 1) / T;
    int gm = (N_NODES + 127) / 128;   // 391

    const int GEMM_SMEM = 65536;
    cudaFuncSetAttribute(k_gemm1, cudaFuncAttributeMaxDynamicSharedMemorySize, GEMM_SMEM);
    cudaFuncSetAttribute(k_gemm2, cudaFuncAttributeMaxDynamicSharedMemorySize, GEMM_SMEM);
    cudaFuncSetAttribute(k_gemm3, cudaFuncAttributeMaxDynamicSharedMemorySize, GEMM_SMEM);

    // serial, single stream
    k_prep<<<(PREP_TOTAL + T - 1) / T, T>>>(ew_raw, dst, x, W1, W2, W3);
    k_scan<<<NCHUNK, SCAN_B>>>();
    k_place<<<nb_edges, T>>>(ew_raw, src, dst);

    k_agg_x<<<agg_blocks, T>>>();
    k_gemm1<<<dim3(gm, 2), 256, GEMM_SMEM>>>(b1);

    k_agg_h<<<agg_blocks, T>>>();
    k_gemm2<<<dim3(gm, 2), 256, GEMM_SMEM>>>(b2);

    k_gemm3<<<dim3(gm, 1), 256, GEMM_SMEM>>>();
    k_agg_out<<<agg_blocks, T>>>(out, b3);
}